// round 1
// baseline (speedup 1.0000x reference)
#include <cuda_runtime.h>
#include <math.h>

// BatchHardTripletLoss: N=8192 points, D=128, fp32. Output: scalar mean loss.
//
// d2[i,j] = ||x_i||^2 + ||x_j||^2 - 2 x_i.x_j + 2*EPS*(s_j - s_i) + D*EPS^2
//         = ci[i] + cj[j] - 2*dot(i,j)
// hardest_pos[i] = max over j: same label, j!=i of dist  (0 if none)
// hardest_neg[i] = min over j: diff label of dist        (always exists)
// loss = mean(relu(hp - hn + MARGIN))
// Selection done in squared-distance space (sqrt monotone) -> 2 sqrts/anchor.

#define NPTS   8192
#define DIM    128
#define MARGIN 0.2f
#define EPSV   1e-6f

#define TILE   128
#define NTILES (NPTS / TILE)        // 64
#define NSPLIT 16
#define JT_PER (NTILES / NSPLIT)    // 4
#define LDA    129                  // padded smem row stride (floats)

__device__ float g_ci[NPTS];
__device__ float g_cj[NPTS];
__device__ float g_hp2[NSPLIT * NPTS];
__device__ float g_hn2[NSPLIT * NPTS];

// ---------------- per-row norms / sums -----------------
__global__ void precompute_kernel(const float* __restrict__ x) {
    int warp = (blockIdx.x * blockDim.x + threadIdx.x) >> 5;
    int lane = threadIdx.x & 31;
    if (warp >= NPTS) return;
    float4 v = *(const float4*)(x + warp * DIM + lane * 4);
    float sq = v.x * v.x + v.y * v.y + v.z * v.z + v.w * v.w;
    float s  = v.x + v.y + v.z + v.w;
    #pragma unroll
    for (int o = 16; o; o >>= 1) {
        sq += __shfl_xor_sync(0xffffffffu, sq, o);
        s  += __shfl_xor_sync(0xffffffffu, s,  o);
    }
    if (lane == 0) {
        g_ci[warp] = sq - 2.0f * EPSV * s;
        g_cj[warp] = sq + 2.0f * EPSV * s + (float)DIM * EPSV * EPSV;
    }
}

// ---------------- fused gram + hardest-pos/neg -----------------
// grid = NTILES * NSPLIT blocks of 256 threads.
// block (bm, split): anchors [bm*128, bm*128+128), j-tiles [split*4, split*4+4).
__global__ void __launch_bounds__(256, 1)
tile_kernel(const float* __restrict__ x, const int* __restrict__ tgt) {
    const int bm    = blockIdx.x & (NTILES - 1);
    const int split = blockIdx.x >> 6;
    const int tid = threadIdx.x;
    const int tx = tid & 15;
    const int ty = tid >> 4;

    extern __shared__ float smem[];
    float* sA = smem;
    float* sB = smem + TILE * LDA;

    const int row0 = bm * TILE;

    // Load A tile (anchors) once: [128 rows][128 k], padded rows.
    #pragma unroll
    for (int it = 0; it < 16; it++) {
        int lin = it * 256 + tid;
        int m = lin >> 5, L = lin & 31;
        float4 v = *(const float4*)(x + (row0 + m) * DIM + 4 * L);
        float* d = sA + m * LDA + 4 * L;
        d[0] = v.x; d[1] = v.y; d[2] = v.z; d[3] = v.w;
    }

    // Per-thread anchor rows: split micro-tile {4ty..4ty+3} U {64+4ty..}.
    int   rloc[8];
    int   gi_r[8];
    float ci_r[8];
    int   ti_r[8];
    #pragma unroll
    for (int u = 0; u < 8; u++) {
        int rr = (u < 4) ? (ty * 4 + u) : (64 + ty * 4 + (u - 4));
        rloc[u] = rr;
        gi_r[u] = row0 + rr;
        ci_r[u] = g_ci[gi_r[u]];
        ti_r[u] = tgt[gi_r[u]];
    }

    float hp2[8], hn2[8];
    #pragma unroll
    for (int u = 0; u < 8; u++) { hp2[u] = 0.0f; hn2[u] = 3.4e38f; }

    const float* pA[8];
    #pragma unroll
    for (int u = 0; u < 8; u++) pA[u] = sA + rloc[u] * LDA;

    for (int jt = split * JT_PER; jt < split * JT_PER + JT_PER; jt++) {
        const int j0 = jt * TILE;
        __syncthreads();  // protect sB from previous iteration's readers
        #pragma unroll
        for (int it = 0; it < 16; it++) {
            int lin = it * 256 + tid;
            int m = lin >> 5, L = lin & 31;
            float4 v = *(const float4*)(x + (j0 + m) * DIM + 4 * L);
            float* d = sB + m * LDA + 4 * L;
            d[0] = v.x; d[1] = v.y; d[2] = v.z; d[3] = v.w;
        }
        __syncthreads();

        int cloc[8];
        const float* pB[8];
        #pragma unroll
        for (int v = 0; v < 8; v++) {
            int cc = (v < 4) ? (tx * 4 + v) : (64 + tx * 4 + (v - 4));
            cloc[v] = cc;
            pB[v] = sB + cc * LDA;
        }

        float acc[8][8];
        #pragma unroll
        for (int u = 0; u < 8; u++)
            #pragma unroll
            for (int v = 0; v < 8; v++) acc[u][v] = 0.0f;

        #pragma unroll 8
        for (int k = 0; k < DIM; k++) {
            float a[8], b[8];
            #pragma unroll
            for (int u = 0; u < 8; u++) a[u] = pA[u][k];
            #pragma unroll
            for (int v = 0; v < 8; v++) b[v] = pB[v][k];
            #pragma unroll
            for (int u = 0; u < 8; u++)
                #pragma unroll
                for (int v = 0; v < 8; v++)
                    acc[u][v] = fmaf(a[u], b[v], acc[u][v]);
        }

        // Epilogue: fold into running hardest-pos/neg (squared space).
        float cj_r[8];
        int   tj_r[8];
        int   gj_r[8];
        #pragma unroll
        for (int v = 0; v < 8; v++) {
            gj_r[v] = j0 + cloc[v];
            cj_r[v] = g_cj[gj_r[v]];
            tj_r[v] = tgt[gj_r[v]];
        }
        #pragma unroll
        for (int u = 0; u < 8; u++) {
            #pragma unroll
            for (int v = 0; v < 8; v++) {
                float d2 = fmaf(-2.0f, acc[u][v], ci_r[u] + cj_r[v]);
                bool same = (ti_r[u] == tj_r[v]);
                if (same) {
                    if (gj_r[v] != gi_r[u] && d2 > hp2[u]) hp2[u] = d2;
                } else {
                    if (d2 < hn2[u]) hn2[u] = d2;
                }
            }
        }
    }

    // Reduce across the 16 tx lanes sharing the same anchor rows.
    #pragma unroll
    for (int o = 1; o < 16; o <<= 1) {
        #pragma unroll
        for (int u = 0; u < 8; u++) {
            hp2[u] = fmaxf(hp2[u], __shfl_xor_sync(0xffffffffu, hp2[u], o));
            hn2[u] = fminf(hn2[u], __shfl_xor_sync(0xffffffffu, hn2[u], o));
        }
    }
    if (tx == 0) {
        #pragma unroll
        for (int u = 0; u < 8; u++) {
            g_hp2[split * NPTS + gi_r[u]] = hp2[u];
            g_hn2[split * NPTS + gi_r[u]] = hn2[u];
        }
    }
}

// ---------------- merge partials + loss + deterministic mean -------------
__global__ void merge_kernel(float* __restrict__ out) {
    __shared__ float ssum[1024];
    float local = 0.0f;
    for (int i = threadIdx.x; i < NPTS; i += 1024) {
        float hp = g_hp2[i];
        float hn = g_hn2[i];
        #pragma unroll
        for (int s = 1; s < NSPLIT; s++) {
            hp = fmaxf(hp, g_hp2[s * NPTS + i]);
            hn = fminf(hn, g_hn2[s * NPTS + i]);
        }
        float l = sqrtf(fmaxf(hp, 0.0f)) - sqrtf(fmaxf(hn, 0.0f)) + MARGIN;
        local += fmaxf(l, 0.0f);
    }
    ssum[threadIdx.x] = local;
    __syncthreads();
    for (int o = 512; o; o >>= 1) {
        if (threadIdx.x < o) ssum[threadIdx.x] += ssum[threadIdx.x + o];
        __syncthreads();
    }
    if (threadIdx.x == 0) out[0] = ssum[0] / (float)NPTS;
}

extern "C" void kernel_launch(void* const* d_in, const int* in_sizes, int n_in,
                              void* d_out, int out_size) {
    const float* x   = (const float*)d_in[0];
    const int*   tgt = (const int*)d_in[1];
    float*       out = (float*)d_out;

    precompute_kernel<<<NPTS / 8, 256>>>(x);

    size_t smem_bytes = 2u * TILE * LDA * sizeof(float);  // 132096
    cudaFuncSetAttribute(tile_kernel,
                         cudaFuncAttributeMaxDynamicSharedMemorySize,
                         (int)smem_bytes);
    tile_kernel<<<NTILES * NSPLIT, 256, smem_bytes>>>(x, tgt);

    merge_kernel<<<1, 1024>>>(out);
}

// round 3
// speedup vs baseline: 3.3102x; 3.3102x over previous
#include <cuda_runtime.h>
#include <cuda_bf16.h>
#include <cstdint>
#include <math.h>

// BatchHardTripletLoss: N=8192, D=128, fp32 in, scalar fp32 out.
// Gram matrix on legacy tensor cores (mma.sync bf16, fp32 accum) via hi/lo
// split: dot = hi.hi' + lo.hi' + hi.lo'  (lo.lo dropped, ~1e-4 abs on d2).
// d2[i,j] = ci[i] + cj[j] - 2 dot; row-wise hardest pos/neg tracked in
// (cj - 2 dot) space, ci added at the end (monotone shift per row).
// Self-pair not excluded: its d2 ~ 0 never wins max over real positives, and
// for singleton labels relu clamps the loss to 0 either way.
// NOTE: tcgen05/TMEM are unavailable (harness targets plain sm_103); this
// uses the portable sm_80 ISA: ldmatrix + mma.sync + cp.async.

#define NPTS   8192
#define DIM    128
#define MARGIN 0.2f
#define EPSV   1e-6f
#define TILE   128
#define NSPLIT 16
#define JT_PER 4                 // 64 j-tiles / NSPLIT
#define NPART  (NSPLIT * 2)      // per (split, warp-n-half) partials

// smem layout (bytes)
#define OFF_AHI  0
#define OFF_ALO  32768
#define OFF_B    65536           // buf b at OFF_B + b*65536: hi, then lo at +32768
#define SMEM_BYTES (OFF_B + 2 * 65536)   // 196608

__device__ float g_ci[NPTS];
__device__ float g_cj[NPTS];
__device__ __align__(16) __nv_bfloat16 g_xhi[NPTS * DIM];
__device__ __align__(16) __nv_bfloat16 g_xlo[NPTS * DIM];
__device__ float g_hp2[NPART * NPTS];
__device__ float g_hn2[NPART * NPTS];

// ---------------- helpers ----------------
__device__ __forceinline__ uint32_t smem_u32(const void* p) {
    uint32_t a;
    asm("{ .reg .u64 t; cvta.to.shared.u64 t, %1; cvt.u32.u64 %0, t; }" : "=r"(a) : "l"(p));
    return a;
}
// swizzled offset of 16B chunk c (0..15) in row r (0..127) of a 128x128 bf16 tile
__device__ __forceinline__ uint32_t t_off(int r, int c) {
    return (uint32_t)(((r >> 3) << 10) + ((c >> 3) << 14) + ((r & 7) << 7)
                      + (((c & 7) ^ (r & 7)) << 4));
}
__device__ __forceinline__ void cp16(uint32_t saddr, const void* gaddr) {
    asm volatile("cp.async.cg.shared.global [%0], [%1], 16;"
                 :: "r"(saddr), "l"(gaddr) : "memory");
}
__device__ __forceinline__ void ldsm4(uint32_t* r, uint32_t addr) {
    asm volatile("ldmatrix.sync.aligned.m8n8.x4.shared.b16 {%0,%1,%2,%3}, [%4];"
                 : "=r"(r[0]), "=r"(r[1]), "=r"(r[2]), "=r"(r[3]) : "r"(addr));
}
__device__ __forceinline__ void mma16816(float* c, const uint32_t* a, const uint32_t* b) {
    asm volatile("mma.sync.aligned.m16n8k16.row.col.f32.bf16.bf16.f32 "
                 "{%0,%1,%2,%3}, {%4,%5,%6,%7}, {%8,%9}, {%0,%1,%2,%3};"
                 : "+f"(c[0]), "+f"(c[1]), "+f"(c[2]), "+f"(c[3])
                 : "r"(a[0]), "r"(a[1]), "r"(a[2]), "r"(a[3]), "r"(b[0]), "r"(b[1]));
}

// ---------------- precompute: ci/cj + bf16 hi/lo split ----------------
__global__ void precompute_kernel(const float* __restrict__ x) {
    int row = (blockIdx.x * blockDim.x + threadIdx.x) >> 5;
    int lane = threadIdx.x & 31;
    float4 v = *(const float4*)(x + (size_t)row * DIM + lane * 4);
    float sq = v.x * v.x + v.y * v.y + v.z * v.z + v.w * v.w;
    float s  = v.x + v.y + v.z + v.w;
    #pragma unroll
    for (int o = 16; o; o >>= 1) {
        sq += __shfl_xor_sync(0xffffffffu, sq, o);
        s  += __shfl_xor_sync(0xffffffffu, s,  o);
    }
    if (lane == 0) {
        g_ci[row] = sq - 2.0f * EPSV * s;
        g_cj[row] = sq + 2.0f * EPSV * s + (float)DIM * EPSV * EPSV;
    }
    __nv_bfloat16 h[4], l[4];
    float vv[4] = {v.x, v.y, v.z, v.w};
    #pragma unroll
    for (int k = 0; k < 4; k++) {
        h[k] = __float2bfloat16(vv[k]);
        l[k] = __float2bfloat16(vv[k] - __bfloat162float(h[k]));
    }
    __nv_bfloat162* dh = (__nv_bfloat162*)(g_xhi + (size_t)row * DIM + lane * 4);
    __nv_bfloat162* dl = (__nv_bfloat162*)(g_xlo + (size_t)row * DIM + lane * 4);
    dh[0] = __halves2bfloat162(h[0], h[1]);
    dh[1] = __halves2bfloat162(h[2], h[3]);
    dl[0] = __halves2bfloat162(l[0], l[1]);
    dl[1] = __halves2bfloat162(l[2], l[3]);
}

// stage a 128x128 bf16 tile pair (hi+lo) into swizzled smem via cp.async
__device__ __forceinline__ void stage_pair(uint32_t shi, uint32_t slo,
                                           int j0, int tid) {
    const char* gh = (const char*)(g_xhi + (size_t)j0 * DIM);
    const char* gl = (const char*)(g_xlo + (size_t)j0 * DIM);
    #pragma unroll
    for (int it = 0; it < 8; it++) {
        int lin = it * 256 + tid;
        uint32_t off = t_off(lin >> 4, lin & 15);
        cp16(shi + off, gh + (size_t)lin * 16);
        cp16(slo + off, gl + (size_t)lin * 16);
    }
}

// ---------------- main fused kernel ----------------
__global__ void __launch_bounds__(256, 1)
tile_kernel(const int* __restrict__ tgt) {
    extern __shared__ char smem[];
    const uint32_t sb = smem_u32(smem);
    const int tid  = threadIdx.x;
    const int lane = tid & 31;
    const int wid  = tid >> 5;
    const int wm = wid & 3;          // 4 warps over M (32 rows each)
    const int wn = wid >> 2;         // 2 warps over N (64 cols each)
    const int bm    = blockIdx.x & 63;
    const int split = blockIdx.x >> 6;
    const int row0  = bm * TILE;

    // stage A (resident) + first B tile
    stage_pair(sb + OFF_AHI, sb + OFF_ALO, row0, tid);
    stage_pair(sb + OFF_B, sb + OFF_B + 32768, (split * JT_PER) * TILE, tid);
    asm volatile("cp.async.commit_group;" ::: "memory");

    // per-thread row constants (C frag: rows t/4 and t/4+8, per 16-row m-tile)
    float civ[2][2];
    int   tiv[2][2];
    const int rbase = row0 + wm * 32 + (lane >> 2);
    #pragma unroll
    for (int mt = 0; mt < 2; mt++)
        #pragma unroll
        for (int so = 0; so < 2; so++) {
            int m = rbase + mt * 16 + so * 8;
            civ[mt][so] = g_ci[m];
            tiv[mt][so] = tgt[m];
        }
    float hp[2][2], hn[2][2];
    #pragma unroll
    for (int mt = 0; mt < 2; mt++)
        #pragma unroll
        for (int so = 0; so < 2; so++) { hp[mt][so] = -3.4e38f; hn[mt][so] = 3.4e38f; }

    // per-lane ldmatrix row indices
    const int ra_lane = (lane & 15);          // A: rows 0..15 within m-tile
    const int ca_add  = (lane >> 4);          // A: k-chunk select
    const int rb_lane = ((lane >> 4) << 3) + (lane & 7);  // B: n within n16-tile
    const int cb_add  = ((lane >> 3) & 1);    // B: k-chunk select

    for (int t = 0; t < JT_PER; t++) {
        const int b = t & 1;
        asm volatile("cp.async.wait_group 0;" ::: "memory");
        __syncthreads();
        if (t + 1 < JT_PER) {
            uint32_t nb = sb + OFF_B + (1 - b) * 65536;
            stage_pair(nb, nb + 32768, (split * JT_PER + t + 1) * TILE, tid);
            asm volatile("cp.async.commit_group;" ::: "memory");
        }

        const uint32_t sAhi = sb + OFF_AHI, sAlo = sb + OFF_ALO;
        const uint32_t sBhi = sb + OFF_B + b * 65536, sBlo = sBhi + 32768;

        float acc[2][8][4];
        #pragma unroll
        for (int mt = 0; mt < 2; mt++)
            #pragma unroll
            for (int n8 = 0; n8 < 8; n8++)
                #pragma unroll
                for (int q = 0; q < 4; q++) acc[mt][n8][q] = 0.0f;

        #pragma unroll
        for (int ks = 0; ks < 8; ks++) {
            uint32_t ah[2][4], al[2][4], bh[4][4], bl[4][4];
            #pragma unroll
            for (int mt = 0; mt < 2; mt++) {
                uint32_t off = t_off(wm * 32 + mt * 16 + ra_lane, 2 * ks + ca_add);
                ldsm4(ah[mt], sAhi + off);
                ldsm4(al[mt], sAlo + off);
            }
            #pragma unroll
            for (int nt = 0; nt < 4; nt++) {
                uint32_t off = t_off(wn * 64 + nt * 16 + rb_lane, 2 * ks + cb_add);
                ldsm4(bh[nt], sBhi + off);
                ldsm4(bl[nt], sBlo + off);
            }
            #pragma unroll
            for (int mt = 0; mt < 2; mt++)
                #pragma unroll
                for (int nt = 0; nt < 4; nt++) {
                    mma16816(acc[mt][2 * nt],     ah[mt], &bh[nt][0]);
                    mma16816(acc[mt][2 * nt + 1], ah[mt], &bh[nt][2]);
                    mma16816(acc[mt][2 * nt],     al[mt], &bh[nt][0]);
                    mma16816(acc[mt][2 * nt + 1], al[mt], &bh[nt][2]);
                    mma16816(acc[mt][2 * nt],     ah[mt], &bl[nt][0]);
                    mma16816(acc[mt][2 * nt + 1], ah[mt], &bl[nt][2]);
                }
        }

        // epilogue: fold cj - 2*dot into running hardest pos/neg
        const int j0 = (split * JT_PER + t) * TILE;
        const int cbase = j0 + wn * 64 + (lane & 3) * 2;
        #pragma unroll
        for (int n8 = 0; n8 < 8; n8++)
            #pragma unroll
            for (int par = 0; par < 2; par++) {
                int j = cbase + n8 * 8 + par;
                float cjv = g_cj[j];
                int   tjv = tgt[j];
                #pragma unroll
                for (int mt = 0; mt < 2; mt++)
                    #pragma unroll
                    for (int so = 0; so < 2; so++) {
                        float tv = fmaf(-2.0f, acc[mt][n8][so * 2 + par], cjv);
                        if (tjv == tiv[mt][so]) hp[mt][so] = fmaxf(hp[mt][so], tv);
                        else                    hn[mt][so] = fminf(hn[mt][so], tv);
                    }
            }
    }

    // reduce across the 4 lanes holding the same rows (lane&3 varies)
    #pragma unroll
    for (int o = 1; o < 4; o <<= 1)
        #pragma unroll
        for (int mt = 0; mt < 2; mt++)
            #pragma unroll
            for (int so = 0; so < 2; so++) {
                hp[mt][so] = fmaxf(hp[mt][so], __shfl_xor_sync(0xffffffffu, hp[mt][so], o));
                hn[mt][so] = fminf(hn[mt][so], __shfl_xor_sync(0xffffffffu, hn[mt][so], o));
            }
    if ((lane & 3) == 0) {
        const int part = split * 2 + wn;
        #pragma unroll
        for (int mt = 0; mt < 2; mt++)
            #pragma unroll
            for (int so = 0; so < 2; so++) {
                int m = rbase + mt * 16 + so * 8;
                g_hp2[part * NPTS + m] = civ[mt][so] + hp[mt][so];
                g_hn2[part * NPTS + m] = civ[mt][so] + hn[mt][so];
            }
    }
}

// ---------------- merge partials -> mean loss ----------------
__global__ void merge_kernel(float* __restrict__ out) {
    __shared__ float ssum[1024];
    float local = 0.0f;
    for (int i = threadIdx.x; i < NPTS; i += 1024) {
        float hp = -3.4e38f, hn = 3.4e38f;
        #pragma unroll
        for (int p = 0; p < NPART; p++) {
            hp = fmaxf(hp, g_hp2[p * NPTS + i]);
            hn = fminf(hn, g_hn2[p * NPTS + i]);
        }
        float l = sqrtf(fmaxf(hp, 0.0f)) - sqrtf(fmaxf(hn, 0.0f)) + MARGIN;
        local += fmaxf(l, 0.0f);
    }
    ssum[threadIdx.x] = local;
    __syncthreads();
    for (int o = 512; o; o >>= 1) {
        if (threadIdx.x < o) ssum[threadIdx.x] += ssum[threadIdx.x + o];
        __syncthreads();
    }
    if (threadIdx.x == 0) out[0] = ssum[0] / (float)NPTS;
}

extern "C" void kernel_launch(void* const* d_in, const int* in_sizes, int n_in,
                              void* d_out, int out_size) {
    const float* x   = (const float*)d_in[0];
    const int*   tgt = (const int*)d_in[1];
    float*       out = (float*)d_out;

    precompute_kernel<<<NPTS / 8, 256>>>(x);

    cudaFuncSetAttribute(tile_kernel,
                         cudaFuncAttributeMaxDynamicSharedMemorySize, SMEM_BYTES);
    tile_kernel<<<64 * NSPLIT, 256, SMEM_BYTES>>>(tgt);

    merge_kernel<<<1, 1024>>>(out);
}

// round 4
// speedup vs baseline: 4.2775x; 1.2922x over previous
#include <cuda_runtime.h>
#include <cuda_bf16.h>
#include <cstdint>
#include <math.h>

// BatchHardTripletLoss: N=8192, D=128, fp32 in, scalar fp32 out.
// Gram on legacy tensor cores (mma.sync bf16 fp32-acc) via hi/lo split:
//   dot = hi.hi' + lo.hi' + hi.lo'  (lo.lo dropped, ~1e-4 abs on d2)
// The computed dot (and d2) is exactly symmetric, so only upper-triangle
// 128x128 tiles are computed (2080 of 4096); each tile is folded twice:
//   row-fold: anchors i (rows),  tv = cj[j] - 2 dot, slot (o=bj, sub=wn)
//   col-fold: anchors j (cols),  tv = cj[i] - 2 dot, slot (o=bi, sub=2+wm)
// Every (slot o, row r) is written exactly once -> no init, no atomics.
// merge adds ci[anchor], takes sqrt, relu, mean.

#define NPTS   8192
#define DIM    128
#define MARGIN 0.2f
#define EPSV   1e-6f
#define TILE   128
#define NTILES 2080              // 64*65/2
#define TPC    4                 // tiles per CTA -> 520 CTAs
#define NSUB   6

// smem layout (bytes)
#define OFF_A    0               // hi at 0, lo at +32768
#define OFF_B    65536           // buf b at OFF_B + b*65536 (hi, lo at +32768)
#define OFF_CJR  196608          // float2[128] row meta (cj, label)
#define OFF_CJC  197632          // float2[2][128] col meta per buffer
#define SMEM_BYTES 199680

__device__ float g_ci[NPTS];
__device__ float g_cj[NPTS];
__device__ __align__(16) __nv_bfloat16 g_xhi[NPTS * DIM];
__device__ __align__(16) __nv_bfloat16 g_xlo[NPTS * DIM];
__device__ float g_php[64 * NSUB * NPTS];
__device__ float g_phn[64 * NSUB * NPTS];
__device__ float g_bsum[32];

// ---------------- helpers ----------------
__device__ __forceinline__ uint32_t smem_u32(const void* p) {
    uint32_t a;
    asm("{ .reg .u64 t; cvta.to.shared.u64 t, %1; cvt.u32.u64 %0, t; }" : "=r"(a) : "l"(p));
    return a;
}
// swizzled offset of 16B chunk c (0..15) in row r (0..127), 128x128 bf16 tile
__device__ __forceinline__ uint32_t t_off(int r, int c) {
    return (uint32_t)(((r >> 3) << 10) + ((c >> 3) << 14) + ((r & 7) << 7)
                      + (((c & 7) ^ (r & 7)) << 4));
}
__device__ __forceinline__ void cp16(uint32_t saddr, const void* gaddr) {
    asm volatile("cp.async.cg.shared.global [%0], [%1], 16;"
                 :: "r"(saddr), "l"(gaddr) : "memory");
}
__device__ __forceinline__ void ldsm4(uint32_t* r, uint32_t addr) {
    asm volatile("ldmatrix.sync.aligned.m8n8.x4.shared.b16 {%0,%1,%2,%3}, [%4];"
                 : "=r"(r[0]), "=r"(r[1]), "=r"(r[2]), "=r"(r[3]) : "r"(addr));
}
__device__ __forceinline__ void mma16816(float* c, const uint32_t* a, const uint32_t* b) {
    asm volatile("mma.sync.aligned.m16n8k16.row.col.f32.bf16.bf16.f32 "
                 "{%0,%1,%2,%3}, {%4,%5,%6,%7}, {%8,%9}, {%0,%1,%2,%3};"
                 : "+f"(c[0]), "+f"(c[1]), "+f"(c[2]), "+f"(c[3])
                 : "r"(a[0]), "r"(a[1]), "r"(a[2]), "r"(a[3]), "r"(b[0]), "r"(b[1]));
}
// tiles before strip b (upper triangle incl. diagonal, 64 blocks)
__device__ __forceinline__ int strip_base(int b) { return b * (129 - b) / 2; }

// ---------------- precompute: ci/cj + bf16 hi/lo split ----------------
__global__ void precompute_kernel(const float* __restrict__ x) {
    int row = (blockIdx.x * blockDim.x + threadIdx.x) >> 5;
    int lane = threadIdx.x & 31;
    float4 v = *(const float4*)(x + (size_t)row * DIM + lane * 4);
    float sq = v.x * v.x + v.y * v.y + v.z * v.z + v.w * v.w;
    float s  = v.x + v.y + v.z + v.w;
    #pragma unroll
    for (int o = 16; o; o >>= 1) {
        sq += __shfl_xor_sync(0xffffffffu, sq, o);
        s  += __shfl_xor_sync(0xffffffffu, s,  o);
    }
    if (lane == 0) {
        g_ci[row] = sq - 2.0f * EPSV * s;
        g_cj[row] = sq + 2.0f * EPSV * s + (float)DIM * EPSV * EPSV;
    }
    __nv_bfloat16 h[4], l[4];
    float vv[4] = {v.x, v.y, v.z, v.w};
    #pragma unroll
    for (int k = 0; k < 4; k++) {
        h[k] = __float2bfloat16(vv[k]);
        l[k] = __float2bfloat16(vv[k] - __bfloat162float(h[k]));
    }
    __nv_bfloat162* dh = (__nv_bfloat162*)(g_xhi + (size_t)row * DIM + lane * 4);
    __nv_bfloat162* dl = (__nv_bfloat162*)(g_xlo + (size_t)row * DIM + lane * 4);
    dh[0] = __halves2bfloat162(h[0], h[1]);
    dh[1] = __halves2bfloat162(h[2], h[3]);
    dl[0] = __halves2bfloat162(l[0], l[1]);
    dl[1] = __halves2bfloat162(l[2], l[3]);
}

// stage a 128x128 bf16 tile pair (hi+lo) into swizzled smem via cp.async
__device__ __forceinline__ void stage_pair(uint32_t shi, int j0, int tid) {
    const char* gh = (const char*)(g_xhi + (size_t)j0 * DIM);
    const char* gl = (const char*)(g_xlo + (size_t)j0 * DIM);
    #pragma unroll
    for (int it = 0; it < 8; it++) {
        int lin = it * 256 + tid;
        uint32_t off = t_off(lin >> 4, lin & 15);
        cp16(shi + off, gh + (size_t)lin * 16);
        cp16(shi + 32768 + off, gl + (size_t)lin * 16);
    }
}

// ---------------- main fused kernel ----------------
__global__ void __launch_bounds__(256, 1)
tile_kernel(const int* __restrict__ tgt) {
    extern __shared__ char smem[];
    const uint32_t sb = smem_u32(smem);
    const int tid  = threadIdx.x;
    const int lane = tid & 31;
    const int wid  = tid >> 5;
    const int wm = wid & 3;          // 4 warps over M
    const int wn = wid >> 2;         // 2 warps over N
    float2* scjr = (float2*)(smem + OFF_CJR);
    float2* scjc = (float2*)(smem + OFF_CJC);

    // this CTA's 4 tiles (linear upper-triangle indices)
    int tb[TPC], tj[TPC];
    #pragma unroll
    for (int s = 0; s < TPC; s++) {
        int t = blockIdx.x * TPC + s;
        int b = (int)(64.5f - sqrtf(64.5f * 64.5f - 2.0f * (float)t));
        if (b < 0) b = 0; if (b > 63) b = 63;
        while (b < 63 && strip_base(b + 1) <= t) b++;
        while (b > 0 && strip_base(b) > t) b--;
        tb[s] = b;
        tj[s] = b + (t - strip_base(b));
    }

    const int ra_lane = (lane & 15);
    const int ca_add  = (lane >> 4);
    const int rb_lane = ((lane >> 4) << 3) + (lane & 7);
    const int cb_add  = ((lane >> 3) & 1);

    int cur_bi = -1;
    bool staged = false;
    for (int s = 0; s < TPC; s++) {
        const int bi = tb[s], bj = tj[s];
        const int b = s & 1;
        if (!staged) {
            if (bi != cur_bi) {
                __syncthreads();                 // everyone done with old A
                stage_pair(sb + OFF_A, bi * TILE, tid);
                if (tid < TILE) {
                    int r = bi * TILE + tid;
                    scjr[tid] = make_float2(g_cj[r], __int_as_float(tgt[r]));
                }
                cur_bi = bi;
            }
            stage_pair(sb + OFF_B + b * 65536, bj * TILE, tid);
            if (tid < TILE) {
                int j = bj * TILE + tid;
                scjc[b * TILE + tid] = make_float2(g_cj[j], __int_as_float(tgt[j]));
            }
            asm volatile("cp.async.commit_group;" ::: "memory");
        }
        asm volatile("cp.async.wait_group 0;" ::: "memory");
        __syncthreads();

        // prefetch next B if same strip (safe: all warps passed the sync)
        bool nextstaged = false;
        if (s + 1 < TPC && tb[s + 1] == cur_bi) {
            int nb = (s + 1) & 1;
            stage_pair(sb + OFF_B + nb * 65536, tj[s + 1] * TILE, tid);
            if (tid < TILE) {
                int j = tj[s + 1] * TILE + tid;
                scjc[nb * TILE + tid] = make_float2(g_cj[j], __int_as_float(tgt[j]));
            }
            asm volatile("cp.async.commit_group;" ::: "memory");
            nextstaged = true;
        }

        // ---------------- 3-pass MMA over K=128 ----------------
        const uint32_t sAhi = sb + OFF_A, sAlo = sAhi + 32768;
        const uint32_t sBhi = sb + OFF_B + b * 65536, sBlo = sBhi + 32768;

        float acc[2][8][4];
        #pragma unroll
        for (int mt = 0; mt < 2; mt++)
            #pragma unroll
            for (int n8 = 0; n8 < 8; n8++)
                #pragma unroll
                for (int q = 0; q < 4; q++) acc[mt][n8][q] = 0.0f;

        #pragma unroll
        for (int ks = 0; ks < 8; ks++) {
            uint32_t ah[2][4], al[2][4], bh[4][4], bl[4][4];
            #pragma unroll
            for (int mt = 0; mt < 2; mt++) {
                uint32_t off = t_off(wm * 32 + mt * 16 + ra_lane, 2 * ks + ca_add);
                ldsm4(ah[mt], sAhi + off);
                ldsm4(al[mt], sAlo + off);
            }
            #pragma unroll
            for (int nt = 0; nt < 4; nt++) {
                uint32_t off = t_off(wn * 64 + nt * 16 + rb_lane, 2 * ks + cb_add);
                ldsm4(bh[nt], sBhi + off);
                ldsm4(bl[nt], sBlo + off);
            }
            #pragma unroll
            for (int mt = 0; mt < 2; mt++)
                #pragma unroll
                for (int nt = 0; nt < 4; nt++) {
                    mma16816(acc[mt][2 * nt],     ah[mt], &bh[nt][0]);
                    mma16816(acc[mt][2 * nt + 1], ah[mt], &bh[nt][2]);
                    mma16816(acc[mt][2 * nt],     al[mt], &bh[nt][0]);
                    mma16816(acc[mt][2 * nt + 1], al[mt], &bh[nt][2]);
                    mma16816(acc[mt][2 * nt],     ah[mt], &bl[nt][0]);
                    mma16816(acc[mt][2 * nt + 1], ah[mt], &bl[nt][2]);
                }
        }

        // ---------------- dual-fold epilogue ----------------
        float cjr[2][2];
        int   tir[2][2];
        #pragma unroll
        for (int mt = 0; mt < 2; mt++)
            #pragma unroll
            for (int so = 0; so < 2; so++) {
                float2 q = scjr[wm * 32 + mt * 16 + so * 8 + (lane >> 2)];
                cjr[mt][so] = q.x;
                tir[mt][so] = __float_as_int(q.y);
            }
        float hpr[2][2], hnr[2][2];
        #pragma unroll
        for (int mt = 0; mt < 2; mt++)
            #pragma unroll
            for (int so = 0; so < 2; so++) { hpr[mt][so] = -3.4e38f; hnr[mt][so] = 3.4e38f; }

        #pragma unroll
        for (int n8 = 0; n8 < 8; n8++) {
            float hpc[2] = {-3.4e38f, -3.4e38f}, hnc[2] = {3.4e38f, 3.4e38f};
            #pragma unroll
            for (int par = 0; par < 2; par++) {
                float2 qc = scjc[b * TILE + wn * 64 + n8 * 8 + (lane & 3) * 2 + par];
                float cjc = qc.x;
                int   tjc = __float_as_int(qc.y);
                #pragma unroll
                for (int mt = 0; mt < 2; mt++)
                    #pragma unroll
                    for (int so = 0; so < 2; so++) {
                        float d = -2.0f * acc[mt][n8][so * 2 + par];
                        float tvr = d + cjc;
                        float tvc = d + cjr[mt][so];
                        if (tjc == tir[mt][so]) {
                            hpr[mt][so] = fmaxf(hpr[mt][so], tvr);
                            hpc[par]    = fmaxf(hpc[par],    tvc);
                        } else {
                            hnr[mt][so] = fminf(hnr[mt][so], tvr);
                            hnc[par]    = fminf(hnc[par],    tvc);
                        }
                    }
            }
            // fold columns across the 8 row-lane groups
            #pragma unroll
            for (int o = 4; o <= 16; o <<= 1)
                #pragma unroll
                for (int par = 0; par < 2; par++) {
                    hpc[par] = fmaxf(hpc[par], __shfl_xor_sync(0xffffffffu, hpc[par], o));
                    hnc[par] = fminf(hnc[par], __shfl_xor_sync(0xffffffffu, hnc[par], o));
                }
            if (lane < 4) {
                #pragma unroll
                for (int par = 0; par < 2; par++) {
                    int j = bj * TILE + wn * 64 + n8 * 8 + lane * 2 + par;
                    g_php[((bi * NSUB) + 2 + wm) * NPTS + j] = hpc[par];
                    g_phn[((bi * NSUB) + 2 + wm) * NPTS + j] = hnc[par];
                }
            }
        }
        // fold rows across the 4 column-lanes
        #pragma unroll
        for (int o = 1; o <= 2; o <<= 1)
            #pragma unroll
            for (int mt = 0; mt < 2; mt++)
                #pragma unroll
                for (int so = 0; so < 2; so++) {
                    hpr[mt][so] = fmaxf(hpr[mt][so], __shfl_xor_sync(0xffffffffu, hpr[mt][so], o));
                    hnr[mt][so] = fminf(hnr[mt][so], __shfl_xor_sync(0xffffffffu, hnr[mt][so], o));
                }
        if ((lane & 3) == 0) {
            #pragma unroll
            for (int mt = 0; mt < 2; mt++)
                #pragma unroll
                for (int so = 0; so < 2; so++) {
                    int r = bi * TILE + wm * 32 + mt * 16 + so * 8 + (lane >> 2);
                    g_php[((bj * NSUB) + wn) * NPTS + r] = hpr[mt][so];
                    g_phn[((bj * NSUB) + wn) * NPTS + r] = hnr[mt][so];
                }
        }
        staged = nextstaged;
    }
}

// ---------------- merge: fold slots -> per-row loss -> block sums ----------
__global__ void merge1_kernel() {
    __shared__ float ssum[256];
    int r = blockIdx.x * 256 + threadIdx.x;
    int blk = r >> 7;
    float hp = -3.4e38f, hn = 3.4e38f;
    for (int o = 0; o < 64; o++) {
        const float* php = g_php + (size_t)o * NSUB * NPTS + r;
        const float* phn = g_phn + (size_t)o * NSUB * NPTS + r;
        if (o >= blk) {
            hp = fmaxf(hp, fmaxf(php[0], php[(size_t)NPTS]));
            hn = fminf(hn, fminf(phn[0], phn[(size_t)NPTS]));
        }
        if (o <= blk) {
            #pragma unroll
            for (int su = 2; su < 6; su++) {
                hp = fmaxf(hp, php[(size_t)su * NPTS]);
                hn = fminf(hn, phn[(size_t)su * NPTS]);
            }
        }
    }
    float ci = g_ci[r];
    float hpd = sqrtf(fmaxf(ci + hp, 0.0f));
    float hnd = sqrtf(fmaxf(ci + hn, 0.0f));
    float loss = fmaxf(hpd - hnd + MARGIN, 0.0f);
    ssum[threadIdx.x] = loss;
    __syncthreads();
    for (int o = 128; o; o >>= 1) {
        if (threadIdx.x < o) ssum[threadIdx.x] += ssum[threadIdx.x + o];
        __syncthreads();
    }
    if (threadIdx.x == 0) g_bsum[blockIdx.x] = ssum[0];
}

__global__ void merge2_kernel(float* __restrict__ out) {
    float v = g_bsum[threadIdx.x];
    #pragma unroll
    for (int o = 16; o; o >>= 1) v += __shfl_xor_sync(0xffffffffu, v, o);
    if (threadIdx.x == 0) out[0] = v / (float)NPTS;
}

extern "C" void kernel_launch(void* const* d_in, const int* in_sizes, int n_in,
                              void* d_out, int out_size) {
    const float* x   = (const float*)d_in[0];
    const int*   tgt = (const int*)d_in[1];
    float*       out = (float*)d_out;

    precompute_kernel<<<NPTS / 8, 256>>>(x);

    cudaFuncSetAttribute(tile_kernel,
                         cudaFuncAttributeMaxDynamicSharedMemorySize, SMEM_BYTES);
    tile_kernel<<<NTILES / TPC, 256, SMEM_BYTES>>>(tgt);

    merge1_kernel<<<NPTS / 256, 256>>>();
    merge2_kernel<<<1, 32>>>(out);
}

// round 5
// speedup vs baseline: 4.5239x; 1.0576x over previous
#include <cuda_runtime.h>
#include <cuda_bf16.h>
#include <cstdint>
#include <math.h>

// BatchHardTripletLoss: N=8192, D=128, fp32 in, scalar fp32 out.
// Gram on legacy tensor cores (mma.sync bf16 fp32-acc) via hi/lo split:
//   dot = hi.hi' + lo.hi' + hi.lo'  (lo.lo dropped, ~1e-4 abs on d2)
// Upper-triangle 128x128 tiles only (2080); each tile folded twice:
//   row-fold: anchors i, tv = cj[j] - 2 dot -> slot (bj, sub=wn)
//   col-fold: anchors j, tv = cj[i] - 2 dot -> slot (bi, sub=2+wm)
// Every (slot, row) written exactly once -> no init, no atomics in tiles.
// TPC=2 -> 1040 CTAs: wave-quantization loss 2.3% (vs 17% at TPC=4).
// merge: fused single kernel (last-block-done), adds ci, sqrt, relu, mean.

#define NPTS   8192
#define DIM    128
#define MARGIN 0.2f
#define EPSV   1e-6f
#define TILE   128
#define NTILES 2080              // 64*65/2
#define TPC    2                 // tiles per CTA -> 1040 CTAs
#define NSUB   6

// smem layout (bytes)
#define OFF_A    0               // hi at 0, lo at +32768
#define OFF_B    65536           // buf b at OFF_B + b*65536 (hi, lo at +32768)
#define OFF_CJR  196608          // float2[128] row meta (cj, label)
#define OFF_CJC  197632          // float2[2][128] col meta per buffer
#define SMEM_BYTES 199680

__device__ float g_ci[NPTS];
__device__ float g_cj[NPTS];
__device__ __align__(16) __nv_bfloat16 g_xhi[NPTS * DIM];
__device__ __align__(16) __nv_bfloat16 g_xlo[NPTS * DIM];
__device__ float g_php[64 * NSUB * NPTS];
__device__ float g_phn[64 * NSUB * NPTS];
__device__ float g_bsum[32];
__device__ int   g_cnt = 0;

// ---------------- helpers ----------------
__device__ __forceinline__ uint32_t smem_u32(const void* p) {
    uint32_t a;
    asm("{ .reg .u64 t; cvta.to.shared.u64 t, %1; cvt.u32.u64 %0, t; }" : "=r"(a) : "l"(p));
    return a;
}
// swizzled offset of 16B chunk c (0..15) in row r (0..127), 128x128 bf16 tile
__device__ __forceinline__ uint32_t t_off(int r, int c) {
    return (uint32_t)(((r >> 3) << 10) + ((c >> 3) << 14) + ((r & 7) << 7)
                      + (((c & 7) ^ (r & 7)) << 4));
}
__device__ __forceinline__ void cp16(uint32_t saddr, const void* gaddr) {
    asm volatile("cp.async.cg.shared.global [%0], [%1], 16;"
                 :: "r"(saddr), "l"(gaddr) : "memory");
}
__device__ __forceinline__ void ldsm4(uint32_t* r, uint32_t addr) {
    asm volatile("ldmatrix.sync.aligned.m8n8.x4.shared.b16 {%0,%1,%2,%3}, [%4];"
                 : "=r"(r[0]), "=r"(r[1]), "=r"(r[2]), "=r"(r[3]) : "r"(addr));
}
__device__ __forceinline__ void mma16816(float* c, const uint32_t* a, const uint32_t* b) {
    asm volatile("mma.sync.aligned.m16n8k16.row.col.f32.bf16.bf16.f32 "
                 "{%0,%1,%2,%3}, {%4,%5,%6,%7}, {%8,%9}, {%0,%1,%2,%3};"
                 : "+f"(c[0]), "+f"(c[1]), "+f"(c[2]), "+f"(c[3])
                 : "r"(a[0]), "r"(a[1]), "r"(a[2]), "r"(a[3]), "r"(b[0]), "r"(b[1]));
}
// tiles before strip b (upper triangle incl. diagonal, 64 blocks)
__device__ __forceinline__ int strip_base(int b) { return b * (129 - b) / 2; }

// ---------------- precompute: ci/cj + bf16 hi/lo split ----------------
__global__ void precompute_kernel(const float* __restrict__ x) {
    int row = (blockIdx.x * blockDim.x + threadIdx.x) >> 5;
    int lane = threadIdx.x & 31;
    float4 v = *(const float4*)(x + (size_t)row * DIM + lane * 4);
    float sq = v.x * v.x + v.y * v.y + v.z * v.z + v.w * v.w;
    float s  = v.x + v.y + v.z + v.w;
    #pragma unroll
    for (int o = 16; o; o >>= 1) {
        sq += __shfl_xor_sync(0xffffffffu, sq, o);
        s  += __shfl_xor_sync(0xffffffffu, s,  o);
    }
    if (lane == 0) {
        g_ci[row] = sq - 2.0f * EPSV * s;
        g_cj[row] = sq + 2.0f * EPSV * s + (float)DIM * EPSV * EPSV;
    }
    __nv_bfloat16 h[4], l[4];
    float vv[4] = {v.x, v.y, v.z, v.w};
    #pragma unroll
    for (int k = 0; k < 4; k++) {
        h[k] = __float2bfloat16(vv[k]);
        l[k] = __float2bfloat16(vv[k] - __bfloat162float(h[k]));
    }
    __nv_bfloat162* dh = (__nv_bfloat162*)(g_xhi + (size_t)row * DIM + lane * 4);
    __nv_bfloat162* dl = (__nv_bfloat162*)(g_xlo + (size_t)row * DIM + lane * 4);
    dh[0] = __halves2bfloat162(h[0], h[1]);
    dh[1] = __halves2bfloat162(h[2], h[3]);
    dl[0] = __halves2bfloat162(l[0], l[1]);
    dl[1] = __halves2bfloat162(l[2], l[3]);
}

// stage a 128x128 bf16 tile pair (hi+lo) into swizzled smem via cp.async
__device__ __forceinline__ void stage_pair(uint32_t shi, int j0, int tid) {
    const char* gh = (const char*)(g_xhi + (size_t)j0 * DIM);
    const char* gl = (const char*)(g_xlo + (size_t)j0 * DIM);
    #pragma unroll
    for (int it = 0; it < 8; it++) {
        int lin = it * 256 + tid;
        uint32_t off = t_off(lin >> 4, lin & 15);
        cp16(shi + off, gh + (size_t)lin * 16);
        cp16(shi + 32768 + off, gl + (size_t)lin * 16);
    }
}

// ---------------- main fused kernel ----------------
__global__ void __launch_bounds__(256, 1)
tile_kernel(const int* __restrict__ tgt) {
    extern __shared__ char smem[];
    const uint32_t sb = smem_u32(smem);
    const int tid  = threadIdx.x;
    const int lane = tid & 31;
    const int wid  = tid >> 5;
    const int wm = wid & 3;          // 4 warps over M
    const int wn = wid >> 2;         // 2 warps over N
    float2* scjr = (float2*)(smem + OFF_CJR);
    float2* scjc = (float2*)(smem + OFF_CJC);

    // this CTA's tiles (linear upper-triangle indices)
    int tb[TPC], tj[TPC];
    #pragma unroll
    for (int s = 0; s < TPC; s++) {
        int t = blockIdx.x * TPC + s;
        int b = (int)(64.5f - sqrtf(64.5f * 64.5f - 2.0f * (float)t));
        if (b < 0) b = 0; if (b > 63) b = 63;
        while (b < 63 && strip_base(b + 1) <= t) b++;
        while (b > 0 && strip_base(b) > t) b--;
        tb[s] = b;
        tj[s] = b + (t - strip_base(b));
    }

    const int ra_lane = (lane & 15);
    const int ca_add  = (lane >> 4);
    const int rb_lane = ((lane >> 4) << 3) + (lane & 7);
    const int cb_add  = ((lane >> 3) & 1);

    int cur_bi = -1;
    bool staged = false;
    for (int s = 0; s < TPC; s++) {
        const int bi = tb[s], bj = tj[s];
        const int b = s & 1;
        if (!staged) {
            if (bi != cur_bi) {
                __syncthreads();                 // everyone done with old A
                stage_pair(sb + OFF_A, bi * TILE, tid);
                if (tid < TILE) {
                    int r = bi * TILE + tid;
                    scjr[tid] = make_float2(g_cj[r], __int_as_float(tgt[r]));
                }
                cur_bi = bi;
            }
            stage_pair(sb + OFF_B + b * 65536, bj * TILE, tid);
            if (tid < TILE) {
                int j = bj * TILE + tid;
                scjc[b * TILE + tid] = make_float2(g_cj[j], __int_as_float(tgt[j]));
            }
            asm volatile("cp.async.commit_group;" ::: "memory");
        }
        asm volatile("cp.async.wait_group 0;" ::: "memory");
        __syncthreads();

        // prefetch next B if same strip (safe: all warps passed the sync)
        bool nextstaged = false;
        if (s + 1 < TPC && tb[s + 1] == cur_bi) {
            int nb = (s + 1) & 1;
            stage_pair(sb + OFF_B + nb * 65536, tj[s + 1] * TILE, tid);
            if (tid < TILE) {
                int j = tj[s + 1] * TILE + tid;
                scjc[nb * TILE + tid] = make_float2(g_cj[j], __int_as_float(tgt[j]));
            }
            asm volatile("cp.async.commit_group;" ::: "memory");
            nextstaged = true;
        }

        // ---------------- 3-pass MMA over K=128 ----------------
        const uint32_t sAhi = sb + OFF_A, sAlo = sAhi + 32768;
        const uint32_t sBhi = sb + OFF_B + b * 65536, sBlo = sBhi + 32768;

        float acc[2][8][4];
        #pragma unroll
        for (int mt = 0; mt < 2; mt++)
            #pragma unroll
            for (int n8 = 0; n8 < 8; n8++)
                #pragma unroll
                for (int q = 0; q < 4; q++) acc[mt][n8][q] = 0.0f;

        #pragma unroll
        for (int ks = 0; ks < 8; ks++) {
            uint32_t ah[2][4], al[2][4], bh[4][4], bl[4][4];
            #pragma unroll
            for (int mt = 0; mt < 2; mt++) {
                uint32_t off = t_off(wm * 32 + mt * 16 + ra_lane, 2 * ks + ca_add);
                ldsm4(ah[mt], sAhi + off);
                ldsm4(al[mt], sAlo + off);
            }
            #pragma unroll
            for (int nt = 0; nt < 4; nt++) {
                uint32_t off = t_off(wn * 64 + nt * 16 + rb_lane, 2 * ks + cb_add);
                ldsm4(bh[nt], sBhi + off);
                ldsm4(bl[nt], sBlo + off);
            }
            #pragma unroll
            for (int mt = 0; mt < 2; mt++)
                #pragma unroll
                for (int nt = 0; nt < 4; nt++) {
                    mma16816(acc[mt][2 * nt],     ah[mt], &bh[nt][0]);
                    mma16816(acc[mt][2 * nt + 1], ah[mt], &bh[nt][2]);
                    mma16816(acc[mt][2 * nt],     al[mt], &bh[nt][0]);
                    mma16816(acc[mt][2 * nt + 1], al[mt], &bh[nt][2]);
                    mma16816(acc[mt][2 * nt],     ah[mt], &bl[nt][0]);
                    mma16816(acc[mt][2 * nt + 1], ah[mt], &bl[nt][2]);
                }
        }

        // ---------------- dual-fold epilogue ----------------
        float cjr[2][2];
        int   tir[2][2];
        #pragma unroll
        for (int mt = 0; mt < 2; mt++)
            #pragma unroll
            for (int so = 0; so < 2; so++) {
                float2 q = scjr[wm * 32 + mt * 16 + so * 8 + (lane >> 2)];
                cjr[mt][so] = q.x;
                tir[mt][so] = __float_as_int(q.y);
            }
        float hpr[2][2], hnr[2][2];
        #pragma unroll
        for (int mt = 0; mt < 2; mt++)
            #pragma unroll
            for (int so = 0; so < 2; so++) { hpr[mt][so] = -3.4e38f; hnr[mt][so] = 3.4e38f; }

        #pragma unroll
        for (int n8 = 0; n8 < 8; n8++) {
            float hpc[2] = {-3.4e38f, -3.4e38f}, hnc[2] = {3.4e38f, 3.4e38f};
            #pragma unroll
            for (int par = 0; par < 2; par++) {
                float2 qc = scjc[b * TILE + wn * 64 + n8 * 8 + (lane & 3) * 2 + par];
                float cjc = qc.x;
                int   tjc = __float_as_int(qc.y);
                #pragma unroll
                for (int mt = 0; mt < 2; mt++)
                    #pragma unroll
                    for (int so = 0; so < 2; so++) {
                        float d = -2.0f * acc[mt][n8][so * 2 + par];
                        float tvr = d + cjc;
                        float tvc = d + cjr[mt][so];
                        if (tjc == tir[mt][so]) {
                            hpr[mt][so] = fmaxf(hpr[mt][so], tvr);
                            hpc[par]    = fmaxf(hpc[par],    tvc);
                        } else {
                            hnr[mt][so] = fminf(hnr[mt][so], tvr);
                            hnc[par]    = fminf(hnc[par],    tvc);
                        }
                    }
            }
            // fold columns across the 8 row-lane groups
            #pragma unroll
            for (int o = 4; o <= 16; o <<= 1)
                #pragma unroll
                for (int par = 0; par < 2; par++) {
                    hpc[par] = fmaxf(hpc[par], __shfl_xor_sync(0xffffffffu, hpc[par], o));
                    hnc[par] = fminf(hnc[par], __shfl_xor_sync(0xffffffffu, hnc[par], o));
                }
            if (lane < 4) {
                #pragma unroll
                for (int par = 0; par < 2; par++) {
                    int j = bj * TILE + wn * 64 + n8 * 8 + lane * 2 + par;
                    g_php[((bi * NSUB) + 2 + wm) * NPTS + j] = hpc[par];
                    g_phn[((bi * NSUB) + 2 + wm) * NPTS + j] = hnc[par];
                }
            }
        }
        // fold rows across the 4 column-lanes
        #pragma unroll
        for (int o = 1; o <= 2; o <<= 1)
            #pragma unroll
            for (int mt = 0; mt < 2; mt++)
                #pragma unroll
                for (int so = 0; so < 2; so++) {
                    hpr[mt][so] = fmaxf(hpr[mt][so], __shfl_xor_sync(0xffffffffu, hpr[mt][so], o));
                    hnr[mt][so] = fminf(hnr[mt][so], __shfl_xor_sync(0xffffffffu, hnr[mt][so], o));
                }
        if ((lane & 3) == 0) {
            #pragma unroll
            for (int mt = 0; mt < 2; mt++)
                #pragma unroll
                for (int so = 0; so < 2; so++) {
                    int r = bi * TILE + wm * 32 + mt * 16 + so * 8 + (lane >> 2);
                    g_php[((bj * NSUB) + wn) * NPTS + r] = hpr[mt][so];
                    g_phn[((bj * NSUB) + wn) * NPTS + r] = hnr[mt][so];
                }
        }
        staged = nextstaged;
    }
}

// ---------------- fused merge: slots -> loss -> mean (last block done) ----
__global__ void merge_kernel(float* __restrict__ out) {
    __shared__ float ssum[256];
    __shared__ bool  last;
    int r = blockIdx.x * 256 + threadIdx.x;
    int blk = r >> 7;
    float hp = -3.4e38f, hn = 3.4e38f;
    for (int o = 0; o < 64; o++) {
        const float* php = g_php + (size_t)o * NSUB * NPTS + r;
        const float* phn = g_phn + (size_t)o * NSUB * NPTS + r;
        if (o >= blk) {
            hp = fmaxf(hp, fmaxf(php[0], php[(size_t)NPTS]));
            hn = fminf(hn, fminf(phn[0], phn[(size_t)NPTS]));
        }
        if (o <= blk) {
            #pragma unroll
            for (int su = 2; su < 6; su++) {
                hp = fmaxf(hp, php[(size_t)su * NPTS]);
                hn = fminf(hn, phn[(size_t)su * NPTS]);
            }
        }
    }
    float ci = g_ci[r];
    float hpd = sqrtf(fmaxf(ci + hp, 0.0f));
    float hnd = sqrtf(fmaxf(ci + hn, 0.0f));
    ssum[threadIdx.x] = fmaxf(hpd - hnd + MARGIN, 0.0f);
    __syncthreads();
    for (int o = 128; o; o >>= 1) {
        if (threadIdx.x < o) ssum[threadIdx.x] += ssum[threadIdx.x + o];
        __syncthreads();
    }
    if (threadIdx.x == 0) {
        g_bsum[blockIdx.x] = ssum[0];
        __threadfence();
        int prev = atomicAdd(&g_cnt, 1);
        last = (prev == gridDim.x - 1);
    }
    __syncthreads();
    if (last && threadIdx.x < 32) {
        float v = g_bsum[threadIdx.x];
        #pragma unroll
        for (int o = 16; o; o >>= 1) v += __shfl_xor_sync(0xffffffffu, v, o);
        if (threadIdx.x == 0) {
            out[0] = v / (float)NPTS;
            g_cnt = 0;   // reset for next graph replay
        }
    }
}

extern "C" void kernel_launch(void* const* d_in, const int* in_sizes, int n_in,
                              void* d_out, int out_size) {
    const float* x   = (const float*)d_in[0];
    const int*   tgt = (const int*)d_in[1];
    float*       out = (float*)d_out;

    precompute_kernel<<<NPTS / 8, 256>>>(x);

    cudaFuncSetAttribute(tile_kernel,
                         cudaFuncAttributeMaxDynamicSharedMemorySize, SMEM_BYTES);
    tile_kernel<<<NTILES / TPC, 256, SMEM_BYTES>>>(tgt);

    merge_kernel<<<NPTS / 256, 256>>>(out);
}

// round 6
// speedup vs baseline: 7.3956x; 1.6348x over previous
#include <cuda_runtime.h>
#include <cuda_bf16.h>
#include <cstdint>
#include <math.h>

// BatchHardTripletLoss: N=8192, D=128, fp32 in, scalar fp32 out.
// Gram on mma.sync bf16 (fp32 acc), 2-pass asymmetric split:
//   dot' = hi_i.hi_j + lo_i.hi_j = x_i.hi_j   (err ~6e-4 on dist, tol 1e-3)
// Upper-triangle 128x128 tiles (2080 CTAs, 1 tile each); dual fold:
//   row-fold: anchors i, tv = cj[j] - 2 dot -> slot (bj, sub=wn)   [shfl]
//   col-fold: anchors j, tv = cj[i] - 2 dot -> slot (bi, sub=2)    [smem]
// 2 CTAs/SM (98KB smem): co-resident CTA hides staging + epilogue.
// Col-fold scratch aliases dead A-lo / B smem after the k-loop.

#define NPTS   8192
#define DIM    128
#define MARGIN 0.2f
#define EPSV   1e-6f
#define TILE   128
#define NCTAS  2080              // 64*65/2
#define NSUB   3

// smem layout (bytes)
#define OFF_AHI  0               // 32 KB
#define OFF_ALO  32768           // 32 KB (hn col-scratch aliases after k-loop)
#define OFF_B    65536           // 32 KB, hi only (hp col-scratch aliases)
#define OFF_CJR  98304           // float2[128] row meta (cj, label)
#define OFF_CJC  99328           // float2[128] col meta
#define SMEM_BYTES 100352

__device__ float g_ci[NPTS];
__device__ float g_cj[NPTS];
__device__ __align__(16) __nv_bfloat16 g_xhi[NPTS * DIM];
__device__ __align__(16) __nv_bfloat16 g_xlo[NPTS * DIM];
__device__ float g_php[64 * NSUB * NPTS];
__device__ float g_phn[64 * NSUB * NPTS];
__device__ float g_bsum[32];
__device__ int   g_cnt = 0;

// ---------------- helpers ----------------
__device__ __forceinline__ uint32_t smem_u32(const void* p) {
    uint32_t a;
    asm("{ .reg .u64 t; cvta.to.shared.u64 t, %1; cvt.u32.u64 %0, t; }" : "=r"(a) : "l"(p));
    return a;
}
// swizzled offset of 16B chunk c (0..15) in row r (0..127), 128x128 bf16 tile
__device__ __forceinline__ uint32_t t_off(int r, int c) {
    return (uint32_t)(((r >> 3) << 10) + ((c >> 3) << 14) + ((r & 7) << 7)
                      + (((c & 7) ^ (r & 7)) << 4));
}
__device__ __forceinline__ void cp16(uint32_t saddr, const void* gaddr) {
    asm volatile("cp.async.cg.shared.global [%0], [%1], 16;"
                 :: "r"(saddr), "l"(gaddr) : "memory");
}
__device__ __forceinline__ void ldsm4(uint32_t* r, uint32_t addr) {
    asm volatile("ldmatrix.sync.aligned.m8n8.x4.shared.b16 {%0,%1,%2,%3}, [%4];"
                 : "=r"(r[0]), "=r"(r[1]), "=r"(r[2]), "=r"(r[3]) : "r"(addr));
}
__device__ __forceinline__ void mma16816(float* c, const uint32_t* a, const uint32_t* b) {
    asm volatile("mma.sync.aligned.m16n8k16.row.col.f32.bf16.bf16.f32 "
                 "{%0,%1,%2,%3}, {%4,%5,%6,%7}, {%8,%9}, {%0,%1,%2,%3};"
                 : "+f"(c[0]), "+f"(c[1]), "+f"(c[2]), "+f"(c[3])
                 : "r"(a[0]), "r"(a[1]), "r"(a[2]), "r"(a[3]), "r"(b[0]), "r"(b[1]));
}
__device__ __forceinline__ int strip_base(int b) { return b * (129 - b) / 2; }

// ---------------- precompute: ci/cj + bf16 hi/lo split ----------------
__global__ void precompute_kernel(const float* __restrict__ x) {
    int row = (blockIdx.x * blockDim.x + threadIdx.x) >> 5;
    int lane = threadIdx.x & 31;
    float4 v = *(const float4*)(x + (size_t)row * DIM + lane * 4);
    float sq = v.x * v.x + v.y * v.y + v.z * v.z + v.w * v.w;
    float s  = v.x + v.y + v.z + v.w;
    #pragma unroll
    for (int o = 16; o; o >>= 1) {
        sq += __shfl_xor_sync(0xffffffffu, sq, o);
        s  += __shfl_xor_sync(0xffffffffu, s,  o);
    }
    if (lane == 0) {
        g_ci[row] = sq - 2.0f * EPSV * s;
        g_cj[row] = sq + 2.0f * EPSV * s + (float)DIM * EPSV * EPSV;
    }
    __nv_bfloat16 h[4], l[4];
    float vv[4] = {v.x, v.y, v.z, v.w};
    #pragma unroll
    for (int k = 0; k < 4; k++) {
        h[k] = __float2bfloat16(vv[k]);
        l[k] = __float2bfloat16(vv[k] - __bfloat162float(h[k]));
    }
    __nv_bfloat162* dh = (__nv_bfloat162*)(g_xhi + (size_t)row * DIM + lane * 4);
    __nv_bfloat162* dl = (__nv_bfloat162*)(g_xlo + (size_t)row * DIM + lane * 4);
    dh[0] = __halves2bfloat162(h[0], h[1]);
    dh[1] = __halves2bfloat162(h[2], h[3]);
    dl[0] = __halves2bfloat162(l[0], l[1]);
    dl[1] = __halves2bfloat162(l[2], l[3]);
}

// ---------------- main fused kernel: one triangle tile per CTA ----------
__global__ void __launch_bounds__(256, 2)
tile_kernel(const int* __restrict__ tgt) {
    extern __shared__ char smem[];
    const uint32_t sb = smem_u32(smem);
    const int tid  = threadIdx.x;
    const int lane = tid & 31;
    const int wid  = tid >> 5;
    const int wm = wid & 3;          // 4 warps over M (32 rows each)
    const int wn = wid >> 2;         // 2 warps over N (64 cols each)
    float2* scjr = (float2*)(smem + OFF_CJR);
    float2* scjc = (float2*)(smem + OFF_CJC);

    // (bi, bj) from linear upper-triangle index
    const int t = blockIdx.x;
    int bi = (int)(64.5f - sqrtf(64.5f * 64.5f - 2.0f * (float)t));
    if (bi < 0) bi = 0; if (bi > 63) bi = 63;
    while (bi < 63 && strip_base(bi + 1) <= t) bi++;
    while (bi > 0 && strip_base(bi) > t) bi--;
    const int bj = bi + (t - strip_base(bi));

    // stage A hi/lo (64 KB) + B hi (32 KB) + meta
    {
        const char* gah = (const char*)(g_xhi + (size_t)bi * TILE * DIM);
        const char* gal = (const char*)(g_xlo + (size_t)bi * TILE * DIM);
        const char* gbh = (const char*)(g_xhi + (size_t)bj * TILE * DIM);
        #pragma unroll
        for (int it = 0; it < 8; it++) {
            int lin = it * 256 + tid;
            uint32_t off = t_off(lin >> 4, lin & 15);
            cp16(sb + OFF_AHI + off, gah + (size_t)lin * 16);
            cp16(sb + OFF_ALO + off, gal + (size_t)lin * 16);
            cp16(sb + OFF_B   + off, gbh + (size_t)lin * 16);
        }
        if (tid < TILE) {
            int r = bi * TILE + tid;
            int j = bj * TILE + tid;
            scjr[tid] = make_float2(g_cj[r], __int_as_float(tgt[r]));
            scjc[tid] = make_float2(g_cj[j], __int_as_float(tgt[j]));
        }
        asm volatile("cp.async.commit_group;" ::: "memory");
    }

    const int ra_lane = (lane & 15);
    const int ca_add  = (lane >> 4);
    const int rb_lane = ((lane >> 4) << 3) + (lane & 7);
    const int cb_add  = ((lane >> 3) & 1);

    asm volatile("cp.async.wait_group 0;" ::: "memory");
    __syncthreads();

    // ---------------- 2-pass MMA over K=128 ----------------
    const uint32_t sAhi = sb + OFF_AHI, sAlo = sb + OFF_ALO, sBhi = sb + OFF_B;

    float acc[2][8][4];
    #pragma unroll
    for (int mt = 0; mt < 2; mt++)
        #pragma unroll
        for (int n8 = 0; n8 < 8; n8++)
            #pragma unroll
            for (int q = 0; q < 4; q++) acc[mt][n8][q] = 0.0f;

    #pragma unroll
    for (int ks = 0; ks < 8; ks++) {
        uint32_t ah[2][4], al[2][4], bh[4][4];
        #pragma unroll
        for (int mt = 0; mt < 2; mt++) {
            uint32_t off = t_off(wm * 32 + mt * 16 + ra_lane, 2 * ks + ca_add);
            ldsm4(ah[mt], sAhi + off);
            ldsm4(al[mt], sAlo + off);
        }
        #pragma unroll
        for (int nt = 0; nt < 4; nt++) {
            uint32_t off = t_off(wn * 64 + nt * 16 + rb_lane, 2 * ks + cb_add);
            ldsm4(bh[nt], sBhi + off);
        }
        #pragma unroll
        for (int mt = 0; mt < 2; mt++)
            #pragma unroll
            for (int nt = 0; nt < 4; nt++) {
                mma16816(acc[mt][2 * nt],     ah[mt], &bh[nt][0]);
                mma16816(acc[mt][2 * nt + 1], ah[mt], &bh[nt][2]);
                mma16816(acc[mt][2 * nt],     al[mt], &bh[nt][0]);
                mma16816(acc[mt][2 * nt + 1], al[mt], &bh[nt][2]);
            }
    }

    __syncthreads();   // all warps done with A-lo / B before scratch aliasing

    // ---------------- dual-fold epilogue ----------------
    float cjr[2][2];
    int   tir[2][2];
    #pragma unroll
    for (int mt = 0; mt < 2; mt++)
        #pragma unroll
        for (int so = 0; so < 2; so++) {
            float2 q = scjr[wm * 32 + mt * 16 + so * 8 + (lane >> 2)];
            cjr[mt][so] = q.x;
            tir[mt][so] = __float_as_int(q.y);
        }
    float hpr[2][2], hnr[2][2];
    #pragma unroll
    for (int mt = 0; mt < 2; mt++)
        #pragma unroll
        for (int so = 0; so < 2; so++) { hpr[mt][so] = -3.4e38f; hnr[mt][so] = 3.4e38f; }

    // col-fold scratch [128 cols][33] over dead smem
    float* scrHp = (float*)(smem + OFF_B);
    float* scrHn = (float*)(smem + OFF_ALO);
    const int group = wm * 8 + (lane >> 2);   // 0..31

    #pragma unroll
    for (int n8 = 0; n8 < 8; n8++) {
        #pragma unroll
        for (int par = 0; par < 2; par++) {
            const int colL = wn * 64 + n8 * 8 + (lane & 3) * 2 + par;
            float2 qc = scjc[colL];
            float cjc = qc.x;
            int   tjc = __float_as_int(qc.y);
            float hpc = -3.4e38f, hnc = 3.4e38f;
            #pragma unroll
            for (int mt = 0; mt < 2; mt++)
                #pragma unroll
                for (int so = 0; so < 2; so++) {
                    float d = -2.0f * acc[mt][n8][so * 2 + par];
                    float tvr = d + cjc;
                    float tvc = d + cjr[mt][so];
                    if (tjc == tir[mt][so]) {
                        hpr[mt][so] = fmaxf(hpr[mt][so], tvr);
                        hpc         = fmaxf(hpc,         tvc);
                    } else {
                        hnr[mt][so] = fminf(hnr[mt][so], tvr);
                        hnc         = fminf(hnc,         tvc);
                    }
                }
            scrHp[colL * 33 + group] = hpc;
            scrHn[colL * 33 + group] = hnc;
        }
    }

    // row fold across the 4 column-lanes, write slot (bj, sub=wn)
    #pragma unroll
    for (int o = 1; o <= 2; o <<= 1)
        #pragma unroll
        for (int mt = 0; mt < 2; mt++)
            #pragma unroll
            for (int so = 0; so < 2; so++) {
                hpr[mt][so] = fmaxf(hpr[mt][so], __shfl_xor_sync(0xffffffffu, hpr[mt][so], o));
                hnr[mt][so] = fminf(hnr[mt][so], __shfl_xor_sync(0xffffffffu, hnr[mt][so], o));
            }
    if ((lane & 3) == 0) {
        #pragma unroll
        for (int mt = 0; mt < 2; mt++)
            #pragma unroll
            for (int so = 0; so < 2; so++) {
                int r = bi * TILE + wm * 32 + mt * 16 + so * 8 + (lane >> 2);
                g_php[((bj * NSUB) + wn) * NPTS + r] = hpr[mt][so];
                g_phn[((bj * NSUB) + wn) * NPTS + r] = hnr[mt][so];
            }
    }

    __syncthreads();   // scratch fully written

    // col fold: thread tid<128 folds hp for column tid; tid>=128 folds hn
    {
        int colL = tid & 127;
        const float* src = (tid < 128) ? scrHp : scrHn;
        float v = src[colL * 33];
        if (tid < 128) {
            #pragma unroll
            for (int gq = 1; gq < 32; gq++) v = fmaxf(v, src[colL * 33 + gq]);
            g_php[((bi * NSUB) + 2) * NPTS + bj * TILE + colL] = v;
        } else {
            #pragma unroll
            for (int gq = 1; gq < 32; gq++) v = fminf(v, src[colL * 33 + gq]);
            g_phn[((bi * NSUB) + 2) * NPTS + bj * TILE + colL] = v;
        }
    }
}

// ---------------- fused merge: slots -> loss -> mean (last block done) ----
__global__ void merge_kernel(float* __restrict__ out) {
    __shared__ float ssum[256];
    __shared__ bool  last;
    int r = blockIdx.x * 256 + threadIdx.x;
    int blk = r >> 7;
    float hp = -3.4e38f, hn = 3.4e38f;
    for (int o = 0; o < 64; o++) {
        const float* php = g_php + (size_t)o * NSUB * NPTS + r;
        const float* phn = g_phn + (size_t)o * NSUB * NPTS + r;
        if (o >= blk) {
            hp = fmaxf(hp, fmaxf(php[0], php[(size_t)NPTS]));
            hn = fminf(hn, fminf(phn[0], phn[(size_t)NPTS]));
        }
        if (o <= blk) {
            hp = fmaxf(hp, php[2 * (size_t)NPTS]);
            hn = fminf(hn, phn[2 * (size_t)NPTS]);
        }
    }
    float ci = g_ci[r];
    float hpd = sqrtf(fmaxf(ci + hp, 0.0f));
    float hnd = sqrtf(fmaxf(ci + hn, 0.0f));
    ssum[threadIdx.x] = fmaxf(hpd - hnd + MARGIN, 0.0f);
    __syncthreads();
    for (int o = 128; o; o >>= 1) {
        if (threadIdx.x < o) ssum[threadIdx.x] += ssum[threadIdx.x + o];
        __syncthreads();
    }
    if (threadIdx.x == 0) {
        g_bsum[blockIdx.x] = ssum[0];
        __threadfence();
        int prev = atomicAdd(&g_cnt, 1);
        last = (prev == gridDim.x - 1);
    }
    __syncthreads();
    if (last && threadIdx.x < 32) {
        float v = g_bsum[threadIdx.x];
        #pragma unroll
        for (int o = 16; o; o >>= 1) v += __shfl_xor_sync(0xffffffffu, v, o);
        if (threadIdx.x == 0) {
            out[0] = v / (float)NPTS;
            g_cnt = 0;   // reset for next graph replay
        }
    }
}

extern "C" void kernel_launch(void* const* d_in, const int* in_sizes, int n_in,
                              void* d_out, int out_size) {
    const float* x   = (const float*)d_in[0];
    const int*   tgt = (const int*)d_in[1];
    float*       out = (float*)d_out;

    precompute_kernel<<<NPTS / 8, 256>>>(x);

    cudaFuncSetAttribute(tile_kernel,
                         cudaFuncAttributeMaxDynamicSharedMemorySize, SMEM_BYTES);
    tile_kernel<<<NCTAS, 256, SMEM_BYTES>>>(tgt);

    merge_kernel<<<NPTS / 256, 256>>>(out);
}

// round 7
// speedup vs baseline: 8.5550x; 1.1568x over previous
#include <cuda_runtime.h>
#include <cuda_fp16.h>
#include <cstdint>
#include <math.h>

// BatchHardTripletLoss: N=8192, D=128, fp32 in, scalar fp32 out.
// Gram on mma.sync fp16 (fp32 acc), SINGLE pass: dot = fp16(x)_i . fp16(x)_j
// (fp16 has 10 mantissa bits: dot err std ~4.5e-3 on d2~256 -> dist err
//  ~3e-4 abs, better than the former 2-pass bf16 split, at half the MMA).
// Upper-triangle 128x128 tiles (2080 CTAs, 1 tile each); dual fold:
//   row-fold: anchors i, tv = cj[j] - 2 dot -> slot (bj, sub=wn)   [shfl]
//   col-fold: anchors j, tv = cj[i] - 2 dot -> slot (bi, sub=2)    [smem]
// 2 CTAs/SM (67.5KB smem): co-resident CTA hides staging + epilogue.
// Col-fold scratch aliases the dead B tile after the k-loop.

#define NPTS   8192
#define DIM    128
#define MARGIN 0.2f
#define EPSV   1e-6f
#define TILE   128
#define NCTAS  2080              // 64*65/2
#define NSUB   3

// smem layout (bytes)
#define OFF_A    0               // 32 KB fp16 A tile
#define OFF_B    32768           // 32 KB fp16 B tile (scratch aliases after k-loop)
#define OFF_CJR  65536           // float2[128] row meta (cj, label)
#define OFF_CJC  66560           // float2[128] col meta
#define SMEM_BYTES 67584
#define SCR_STRIDE 18            // 16 groups + pad -> conflict-free
#define SCR_HN_OFF (128 * SCR_STRIDE * 4)   // 9216 B

__device__ float g_ci[NPTS];
__device__ float g_cj[NPTS];
__device__ __align__(16) __half g_xh[NPTS * DIM];
__device__ float g_php[64 * NSUB * NPTS];
__device__ float g_phn[64 * NSUB * NPTS];
__device__ float g_bsum[32];
__device__ int   g_cnt = 0;

// ---------------- helpers ----------------
__device__ __forceinline__ uint32_t smem_u32(const void* p) {
    uint32_t a;
    asm("{ .reg .u64 t; cvta.to.shared.u64 t, %1; cvt.u32.u64 %0, t; }" : "=r"(a) : "l"(p));
    return a;
}
// swizzled offset of 16B chunk c (0..15) in row r (0..127), 128x128 f16 tile
__device__ __forceinline__ uint32_t t_off(int r, int c) {
    return (uint32_t)(((r >> 3) << 10) + ((c >> 3) << 14) + ((r & 7) << 7)
                      + (((c & 7) ^ (r & 7)) << 4));
}
__device__ __forceinline__ void cp16(uint32_t saddr, const void* gaddr) {
    asm volatile("cp.async.cg.shared.global [%0], [%1], 16;"
                 :: "r"(saddr), "l"(gaddr) : "memory");
}
__device__ __forceinline__ void ldsm4(uint32_t* r, uint32_t addr) {
    asm volatile("ldmatrix.sync.aligned.m8n8.x4.shared.b16 {%0,%1,%2,%3}, [%4];"
                 : "=r"(r[0]), "=r"(r[1]), "=r"(r[2]), "=r"(r[3]) : "r"(addr));
}
__device__ __forceinline__ void mma16816(float* c, const uint32_t* a, const uint32_t* b) {
    asm volatile("mma.sync.aligned.m16n8k16.row.col.f32.f16.f16.f32 "
                 "{%0,%1,%2,%3}, {%4,%5,%6,%7}, {%8,%9}, {%0,%1,%2,%3};"
                 : "+f"(c[0]), "+f"(c[1]), "+f"(c[2]), "+f"(c[3])
                 : "r"(a[0]), "r"(a[1]), "r"(a[2]), "r"(a[3]), "r"(b[0]), "r"(b[1]));
}
__device__ __forceinline__ int strip_base(int b) { return b * (129 - b) / 2; }

// ---------------- precompute: ci/cj + fp16 conversion (2 rows/warp) ------
__global__ void precompute_kernel(const float* __restrict__ x) {
    int w = (blockIdx.x * blockDim.x + threadIdx.x) >> 5;
    int lane = threadIdx.x & 31;
    int row0 = w * 2;
    float4 v0 = *(const float4*)(x + (size_t)row0 * DIM + lane * 4);
    float4 v1 = *(const float4*)(x + (size_t)(row0 + 1) * DIM + lane * 4);
    #pragma unroll
    for (int r = 0; r < 2; r++) {
        float4 v = r ? v1 : v0;
        int row = row0 + r;
        float sq = v.x * v.x + v.y * v.y + v.z * v.z + v.w * v.w;
        float s  = v.x + v.y + v.z + v.w;
        #pragma unroll
        for (int o = 16; o; o >>= 1) {
            sq += __shfl_xor_sync(0xffffffffu, sq, o);
            s  += __shfl_xor_sync(0xffffffffu, s,  o);
        }
        if (lane == 0) {
            g_ci[row] = sq - 2.0f * EPSV * s;
            g_cj[row] = sq + 2.0f * EPSV * s + (float)DIM * EPSV * EPSV;
        }
        __half2* dh = (__half2*)(g_xh + (size_t)row * DIM + lane * 4);
        dh[0] = __floats2half2_rn(v.x, v.y);
        dh[1] = __floats2half2_rn(v.z, v.w);
    }
}

// ---------------- main fused kernel: one triangle tile per CTA ----------
__global__ void __launch_bounds__(256, 2)
tile_kernel(const int* __restrict__ tgt) {
    extern __shared__ char smem[];
    const uint32_t sb = smem_u32(smem);
    const int tid  = threadIdx.x;
    const int lane = tid & 31;
    const int wid  = tid >> 5;
    const int wm = wid & 3;          // 4 warps over M (32 rows each)
    const int wn = wid >> 2;         // 2 warps over N (64 cols each)
    float2* scjr = (float2*)(smem + OFF_CJR);
    float2* scjc = (float2*)(smem + OFF_CJC);

    // (bi, bj) from linear upper-triangle index
    const int t = blockIdx.x;
    int bi = (int)(64.5f - sqrtf(64.5f * 64.5f - 2.0f * (float)t));
    if (bi < 0) bi = 0; if (bi > 63) bi = 63;
    while (bi < 63 && strip_base(bi + 1) <= t) bi++;
    while (bi > 0 && strip_base(bi) > t) bi--;
    const int bj = bi + (t - strip_base(bi));

    // stage A (32 KB) + B (32 KB) + meta
    {
        const char* ga = (const char*)(g_xh + (size_t)bi * TILE * DIM);
        const char* gb = (const char*)(g_xh + (size_t)bj * TILE * DIM);
        #pragma unroll
        for (int it = 0; it < 8; it++) {
            int lin = it * 256 + tid;
            uint32_t off = t_off(lin >> 4, lin & 15);
            cp16(sb + OFF_A + off, ga + (size_t)lin * 16);
            cp16(sb + OFF_B + off, gb + (size_t)lin * 16);
        }
        if (tid < TILE) {
            int r = bi * TILE + tid;
            int j = bj * TILE + tid;
            scjr[tid] = make_float2(g_cj[r], __int_as_float(tgt[r]));
            scjc[tid] = make_float2(g_cj[j], __int_as_float(tgt[j]));
        }
        asm volatile("cp.async.commit_group;" ::: "memory");
    }

    const int ra_lane = (lane & 15);
    const int ca_add  = (lane >> 4);
    const int rb_lane = ((lane >> 4) << 3) + (lane & 7);
    const int cb_add  = ((lane >> 3) & 1);

    asm volatile("cp.async.wait_group 0;" ::: "memory");
    __syncthreads();

    // ---------------- single-pass MMA over K=128 ----------------
    const uint32_t sA = sb + OFF_A, sB = sb + OFF_B;

    float acc[2][8][4];
    #pragma unroll
    for (int mt = 0; mt < 2; mt++)
        #pragma unroll
        for (int n8 = 0; n8 < 8; n8++)
            #pragma unroll
            for (int q = 0; q < 4; q++) acc[mt][n8][q] = 0.0f;

    #pragma unroll
    for (int ks = 0; ks < 8; ks++) {
        uint32_t ah[2][4], bh[4][4];
        #pragma unroll
        for (int mt = 0; mt < 2; mt++) {
            uint32_t off = t_off(wm * 32 + mt * 16 + ra_lane, 2 * ks + ca_add);
            ldsm4(ah[mt], sA + off);
        }
        #pragma unroll
        for (int nt = 0; nt < 4; nt++) {
            uint32_t off = t_off(wn * 64 + nt * 16 + rb_lane, 2 * ks + cb_add);
            ldsm4(bh[nt], sB + off);
        }
        #pragma unroll
        for (int mt = 0; mt < 2; mt++)
            #pragma unroll
            for (int nt = 0; nt < 4; nt++) {
                mma16816(acc[mt][2 * nt],     ah[mt], &bh[nt][0]);
                mma16816(acc[mt][2 * nt + 1], ah[mt], &bh[nt][2]);
            }
    }

    __syncthreads();   // all warps done with B before scratch aliasing

    // ---------------- dual-fold epilogue ----------------
    float cjr[2][2];
    int   tir[2][2];
    #pragma unroll
    for (int mt = 0; mt < 2; mt++)
        #pragma unroll
        for (int so = 0; so < 2; so++) {
            float2 q = scjr[wm * 32 + mt * 16 + so * 8 + (lane >> 2)];
            cjr[mt][so] = q.x;
            tir[mt][so] = __float_as_int(q.y);
        }
    float hpr[2][2], hnr[2][2];
    #pragma unroll
    for (int mt = 0; mt < 2; mt++)
        #pragma unroll
        for (int so = 0; so < 2; so++) { hpr[mt][so] = -3.4e38f; hnr[mt][so] = 3.4e38f; }

    // col-fold scratch over dead B tile: [128 cols][18] per array
    float* scrHp = (float*)(smem + OFF_B);
    float* scrHn = (float*)(smem + OFF_B + SCR_HN_OFF);
    const int g16 = wm * 4 + (lane >> 3);          // group after 1-round shfl fold
    const bool keep = ((lane >> 2) & 1) == 0;

    #pragma unroll
    for (int n8 = 0; n8 < 8; n8++) {
        #pragma unroll
        for (int par = 0; par < 2; par++) {
            const int colL = wn * 64 + n8 * 8 + (lane & 3) * 2 + par;
            float2 qc = scjc[colL];
            float cjc = qc.x;
            int   tjc = __float_as_int(qc.y);
            float hpc = -3.4e38f, hnc = 3.4e38f;
            #pragma unroll
            for (int mt = 0; mt < 2; mt++)
                #pragma unroll
                for (int so = 0; so < 2; so++) {
                    float d = -2.0f * acc[mt][n8][so * 2 + par];
                    float tvr = d + cjc;
                    float tvc = d + cjr[mt][so];
                    if (tjc == tir[mt][so]) {
                        hpr[mt][so] = fmaxf(hpr[mt][so], tvr);
                        hpc         = fmaxf(hpc,         tvc);
                    } else {
                        hnr[mt][so] = fminf(hnr[mt][so], tvr);
                        hnc         = fminf(hnc,         tvc);
                    }
                }
            // fold group pairs (lane>>2 even/odd) before scratch
            hpc = fmaxf(hpc, __shfl_xor_sync(0xffffffffu, hpc, 4));
            hnc = fminf(hnc, __shfl_xor_sync(0xffffffffu, hnc, 4));
            if (keep) {
                scrHp[colL * SCR_STRIDE + g16] = hpc;
                scrHn[colL * SCR_STRIDE + g16] = hnc;
            }
        }
    }

    // row fold across the 4 column-lanes, write slot (bj, sub=wn)
    #pragma unroll
    for (int o = 1; o <= 2; o <<= 1)
        #pragma unroll
        for (int mt = 0; mt < 2; mt++)
            #pragma unroll
            for (int so = 0; so < 2; so++) {
                hpr[mt][so] = fmaxf(hpr[mt][so], __shfl_xor_sync(0xffffffffu, hpr[mt][so], o));
                hnr[mt][so] = fminf(hnr[mt][so], __shfl_xor_sync(0xffffffffu, hnr[mt][so], o));
            }
    if ((lane & 3) == 0) {
        #pragma unroll
        for (int mt = 0; mt < 2; mt++)
            #pragma unroll
            for (int so = 0; so < 2; so++) {
                int r = bi * TILE + wm * 32 + mt * 16 + so * 8 + (lane >> 2);
                g_php[((bj * NSUB) + wn) * NPTS + r] = hpr[mt][so];
                g_phn[((bj * NSUB) + wn) * NPTS + r] = hnr[mt][so];
            }
    }

    __syncthreads();   // scratch fully written

    // col fold: tid<128 folds hp for column tid; tid>=128 folds hn
    {
        int colL = tid & 127;
        const float* src = (tid < 128) ? scrHp : scrHn;
        float v = src[colL * SCR_STRIDE];
        if (tid < 128) {
            #pragma unroll
            for (int gq = 1; gq < 16; gq++) v = fmaxf(v, src[colL * SCR_STRIDE + gq]);
            g_php[((bi * NSUB) + 2) * NPTS + bj * TILE + colL] = v;
        } else {
            #pragma unroll
            for (int gq = 1; gq < 16; gq++) v = fminf(v, src[colL * SCR_STRIDE + gq]);
            g_phn[((bi * NSUB) + 2) * NPTS + bj * TILE + colL] = v;
        }
    }
}

// ---------------- fused merge: slots -> loss -> mean (last block done) ----
__global__ void merge_kernel(float* __restrict__ out) {
    __shared__ float ssum[256];
    __shared__ bool  last;
    int r = blockIdx.x * 256 + threadIdx.x;
    int blk = r >> 7;
    float hp = -3.4e38f, hn = 3.4e38f;
    for (int o = 0; o < 64; o++) {
        const float* php = g_php + (size_t)o * NSUB * NPTS + r;
        const float* phn = g_phn + (size_t)o * NSUB * NPTS + r;
        if (o >= blk) {
            hp = fmaxf(hp, fmaxf(php[0], php[(size_t)NPTS]));
            hn = fminf(hn, fminf(phn[0], phn[(size_t)NPTS]));
        }
        if (o <= blk) {
            hp = fmaxf(hp, php[2 * (size_t)NPTS]);
            hn = fminf(hn, phn[2 * (size_t)NPTS]);
        }
    }
    float ci = g_ci[r];
    float hpd = sqrtf(fmaxf(ci + hp, 0.0f));
    float hnd = sqrtf(fmaxf(ci + hn, 0.0f));
    ssum[threadIdx.x] = fmaxf(hpd - hnd + MARGIN, 0.0f);
    __syncthreads();
    for (int o = 128; o; o >>= 1) {
        if (threadIdx.x < o) ssum[threadIdx.x] += ssum[threadIdx.x + o];
        __syncthreads();
    }
    if (threadIdx.x == 0) {
        g_bsum[blockIdx.x] = ssum[0];
        __threadfence();
        int prev = atomicAdd(&g_cnt, 1);
        last = (prev == gridDim.x - 1);
    }
    __syncthreads();
    if (last && threadIdx.x < 32) {
        float v = g_bsum[threadIdx.x];
        #pragma unroll
        for (int o = 16; o; o >>= 1) v += __shfl_xor_sync(0xffffffffu, v, o);
        if (threadIdx.x == 0) {
            out[0] = v / (float)NPTS;
            g_cnt = 0;   // reset for next graph replay
        }
    }
}

extern "C" void kernel_launch(void* const* d_in, const int* in_sizes, int n_in,
                              void* d_out, int out_size) {
    const float* x   = (const float*)d_in[0];
    const int*   tgt = (const int*)d_in[1];
    float*       out = (float*)d_out;

    precompute_kernel<<<NPTS / 16, 256>>>(x);

    cudaFuncSetAttribute(tile_kernel,
                         cudaFuncAttributeMaxDynamicSharedMemorySize, SMEM_BYTES);
    tile_kernel<<<NCTAS, 256, SMEM_BYTES>>>(tgt);

    merge_kernel<<<NPTS / 256, 256>>>(out);
}